// round 15
// baseline (speedup 1.0000x reference)
#include <cuda_runtime.h>
#include <cuda_fp16.h>
#include <cstdint>
#include <math.h>

#define B_  16
#define S_  4096
#define D_  512
#define DH_ 256
#define M_  (B_ * S_)   // 65536
#define CL_ 128
#define NC_ 32

// Scratch (device globals; allocation-free per harness rules)
__device__ __half g_h[(size_t)M_ * DH_];       // 32 MB intermediate h (fp16)
__device__ float  g_carry[B_ * NC_ * D_];
__device__ float  g_cvs[B_ * NC_ * D_];
__device__ __half g_w1t[DH_ * D_];             // W1^T [256,512] (n-major, k-contig)
__device__ __half g_w2t[D_ * DH_];             // W2^T [512,256]

// ===========================================================================
// helpers
// ===========================================================================
__device__ __forceinline__ uint32_t smem_u32(const void* p) {
    uint32_t a;
    asm("{ .reg .u64 t; cvta.to.shared.u64 t, %1; cvt.u32.u64 %0, t; }"
        : "=r"(a) : "l"(p));
    return a;
}

__device__ __forceinline__ uint32_t h2u(__half2 v) {
    uint32_t u;
    __builtin_memcpy(&u, &v, 4);
    return u;
}

__device__ __forceinline__ float2 u2f2(uint32_t u) {
    __half2 h;
    __builtin_memcpy(&h, &u, 4);
    return __half22float2(h);
}

__device__ __forceinline__ void cp16(uint32_t dst, const void* src) {
    asm volatile("cp.async.cg.shared.global [%0], [%1], 16;" :: "r"(dst), "l"(src));
}
#define CP_COMMIT() asm volatile("cp.async.commit_group;" ::: "memory")
#define CP_WAIT(n)  asm volatile("cp.async.wait_group %0;" :: "n"(n) : "memory")

#define LDSM_X4(r0, r1, r2, r3, addr) \
    asm volatile("ldmatrix.sync.aligned.m8n8.x4.shared.b16 {%0,%1,%2,%3}, [%4];" \
        : "=r"(r0), "=r"(r1), "=r"(r2), "=r"(r3) : "r"(addr))

#define MMA16816(acc, a, b0, b1) \
    asm volatile( \
        "mma.sync.aligned.m16n8k16.row.col.f32.f16.f16.f32 " \
        "{%0,%1,%2,%3},{%4,%5,%6,%7},{%8,%9},{%0,%1,%2,%3};" \
        : "+f"((acc)[0]), "+f"((acc)[1]), "+f"((acc)[2]), "+f"((acc)[3]) \
        : "r"((a)[0]), "r"((a)[1]), "r"((a)[2]), "r"((a)[3]), \
          "r"(b0), "r"(b1))

// fp16-accumulator variant: D/C are 2 regs of f16x2
#define MMA16816H(d, a, b0, b1) \
    asm volatile( \
        "mma.sync.aligned.m16n8k16.row.col.f16.f16.f16.f16 " \
        "{%0,%1},{%2,%3,%4,%5},{%6,%7},{%0,%1};" \
        : "+r"((d)[0]), "+r"((d)[1]) \
        : "r"((a)[0]), "r"((a)[1]), "r"((a)[2]), "r"((a)[3]), \
          "r"(b0), "r"(b1))

// fast softplus: max(z,0) + log(1 + exp(-|z|)) via MUFU intrinsics
__device__ __forceinline__ float softplus_f(float z) {
    return fmaxf(z, 0.f) + __logf(1.f + __expf(-fabsf(z)));
}

// ===========================================================================
// GARCH carry pass (float4: 4 independent chains per thread, LDG.128)
// ===========================================================================
__global__ void __launch_bounds__(256) garch_carry_kernel(
    const float* __restrict__ ret,
    const float* __restrict__ pa, const float* __restrict__ pb,
    const float* __restrict__ pw)
{
    const int t  = blockIdx.x * 256 + threadIdx.x;   // 0..65535
    const int d4 = t & 127;
    const int c  = (t >> 7) & (NC_ - 1);
    const int b  = t >> 12;
    const float alpha = pa[0], beta = pb[0], omega = pw[0];
    const float4* rp = (const float4*)ret
                     + ((size_t)b * S_ + (size_t)c * CL_) * (D_ / 4) + d4;
    float4 p = make_float4(0.f, 0.f, 0.f, 0.f);
#pragma unroll 8
    for (int k = 0; k < CL_; ++k) {
        float4 r = rp[(size_t)k * (D_ / 4)];
        p.x = fmaf(beta, p.x, fmaf(alpha, r.x * r.x, omega));
        p.y = fmaf(beta, p.y, fmaf(alpha, r.y * r.y, omega));
        p.z = fmaf(beta, p.z, fmaf(alpha, r.z * r.z, omega));
        p.w = fmaf(beta, p.w, fmaf(alpha, r.w * r.w, omega));
    }
    ((float4*)g_carry)[(((b << 5) + c) << 7) + d4] = p;
}

// ===========================================================================
// GARCH scan: preload all 32 carries (MLP=32), then register scan.
// ===========================================================================
__global__ void __launch_bounds__(256) garch_scan_kernel(const float* __restrict__ pb)
{
    const int t = blockIdx.x * 256 + threadIdx.x;
    const int b = t >> 9;
    const int d = t & (D_ - 1);
    const float beta = pb[0];
    float A = 1.f;
#pragma unroll
    for (int i = 0; i < CL_; ++i) A *= beta;

    float ca[NC_];
#pragma unroll
    for (int c = 0; c < NC_; ++c)
        ca[c] = g_carry[(((b << 5) + c) << 9) + d];

    float cvs = 0.01f;
#pragma unroll
    for (int c = 0; c < NC_; ++c) {
        g_cvs[(((b << 5) + c) << 9) + d] = cvs;
        cvs = fmaf(A, cvs, ca[c]);
    }
}

// ===========================================================================
// Weight transpose [K,N] fp32 -> [N,K] fp16
// ===========================================================================
__global__ void transpose_h_kernel(const float* __restrict__ src, __half* __restrict__ dst,
                                   int K, int N)
{
    __shared__ float t[32][33];
    const int kb = blockIdx.x * 32, nb = blockIdx.y * 32;
    for (int i = threadIdx.y; i < 32; i += 8)
        t[i][threadIdx.x] = src[(size_t)(kb + i) * N + nb + threadIdx.x];
    __syncthreads();
    for (int i = threadIdx.y; i < 32; i += 8)
        dst[(size_t)(nb + i) * K + kb + threadIdx.x] = __float2half(t[threadIdx.x][i]);
}

// common geometry
#define ROWB 144                          // fp16 smem row stride (bytes)
#define TILE_BYTES (128 * ROWB)           // 18432 (128 rows)

// ===========================================================================
// GEMM1 (proven R13): h = relu(x @ W1 + b1). Tile 64x256, 256 thr, 2 CTAs/SM.
// ===========================================================================
#define G1_BK 64
#define G1_A_ROWS 64
#define G1_A16_ST (G1_A_ROWS * ROWB)               // 9216, 2 stages
#define G1_B_ROWS 256
#define G1_B_ST (G1_B_ROWS * ROWB)                 // 36864, 2 stages
#define G1_SMEM (2 * G1_A16_ST + 2 * G1_B_ST)      // 92160

__global__ void __launch_bounds__(256, 2) gemm1_tc(
    const float* __restrict__ X, const __half* __restrict__ Bt,
    const float* __restrict__ bias, __half* __restrict__ C)
{
    extern __shared__ char smraw[];
    const uint32_t sbase = smem_u32(smraw);
    const uint32_t a16b  = sbase;                   // 2 x 9216
    const uint32_t bb    = sbase + 2 * G1_A16_ST;   // 2 x 36864
    __shared__ float bias_sm[256];

    const int tid  = threadIdx.x;
    const int lane = tid & 31;
    const int warp = tid >> 5;
    const int wm   = (warp >> 2) * 32;    // 2x4 warp grid, 32x64 per warp
    const int wn   = (warp & 3) * 64;
    const int gid  = lane >> 2;
    const int tig  = lane & 3;
    const int bm0  = blockIdx.y * G1_A_ROWS;
    const int nk   = D_ / G1_BK;          // 8

    bias_sm[tid] = bias[tid];

    float acc[2][8][4];
#pragma unroll
    for (int mt = 0; mt < 2; ++mt)
#pragma unroll
        for (int nt = 0; nt < 8; ++nt)
#pragma unroll
            for (int i = 0; i < 4; ++i) acc[mt][nt][i] = 0.f;

    auto load_B = [&](int kt) {
        const uint32_t tb = bb + (uint32_t)((kt & 1) * G1_B_ST);
#pragma unroll
        for (int i = 0; i < 8; ++i) {          // 2048 16B chunks
            const int id = tid + i * 256;
            const int r = id >> 3, s = id & 7;
            cp16(tb + r * ROWB + s * 16,
                 Bt + (size_t)r * D_ + kt * G1_BK + s * 8);
        }
        CP_COMMIT();
    };

    const int arow = tid >> 2;            // 0..63
    const int aq   = tid & 3;
    const float* Xrow = X + (size_t)(bm0 + arow) * D_ + aq * 16;
    const uint32_t a16w = (uint32_t)(arow * ROWB + aq * 32);   // 16 halves

    auto ldg_A = [&](int kt, float4* pf) {
#pragma unroll
        for (int i = 0; i < 4; ++i)
            pf[i] = *(const float4*)(Xrow + kt * G1_BK + i * 4);
    };
    auto sts_A = [&](int kt, const float4* pf) {
        const uint32_t dst = a16b + (uint32_t)((kt & 1) * G1_A16_ST) + a16w;
        uint32_t h[8];
#pragma unroll
        for (int i = 0; i < 4; ++i) {
            h[2 * i]     = h2u(__floats2half2_rn(pf[i].x, pf[i].y));
            h[2 * i + 1] = h2u(__floats2half2_rn(pf[i].z, pf[i].w));
        }
        asm volatile("st.shared.v4.b32 [%0], {%1,%2,%3,%4};"
                     :: "r"(dst), "r"(h[0]), "r"(h[1]), "r"(h[2]), "r"(h[3]));
        asm volatile("st.shared.v4.b32 [%0], {%1,%2,%3,%4};"
                     :: "r"(dst + 16), "r"(h[4]), "r"(h[5]), "r"(h[6]), "r"(h[7]));
    };

    load_B(0);
    {
        float4 pf[4];
        ldg_A(0, pf);
        sts_A(0, pf);
    }

    const int half = lane >> 3;
    const uint32_t laneA = (uint32_t)((wm + (lane & 7) + (half & 1) * 8) * ROWB
                                      + (half >> 1) * 16);
    const uint32_t laneB = (uint32_t)((wn + (lane & 7) + ((lane >> 4) << 3)) * ROWB
                                      + ((half & 1) * 16));

    for (int kt = 0; kt < nk; ++kt) {
        CP_WAIT(0);
        __syncthreads();

        float4 pf[4];
        if (kt + 1 < nk) {
            ldg_A(kt + 1, pf);
            load_B(kt + 1);
        }

        const uint32_t aB = a16b + (uint32_t)((kt & 1) * G1_A16_ST);
        const uint32_t bB = bb + (uint32_t)((kt & 1) * G1_B_ST);

#pragma unroll
        for (int q = 0; q < 4; ++q) {
            uint32_t af[2][4];
#pragma unroll
            for (int mt = 0; mt < 2; ++mt)
                LDSM_X4(af[mt][0], af[mt][1], af[mt][2], af[mt][3],
                        aB + laneA + mt * (16 * ROWB) + q * 32);
#pragma unroll
            for (int p = 0; p < 4; ++p) {
                uint32_t bf[4];
                LDSM_X4(bf[0], bf[1], bf[2], bf[3],
                        bB + laneB + p * (16 * ROWB) + q * 32);
#pragma unroll
                for (int mt = 0; mt < 2; ++mt) {
                    MMA16816(acc[mt][2 * p],     af[mt], bf[0], bf[1]);
                    MMA16816(acc[mt][2 * p + 1], af[mt], bf[2], bf[3]);
                }
            }
        }

        if (kt + 1 < nk) sts_A(kt + 1, pf);
    }

#pragma unroll
    for (int mt = 0; mt < 2; ++mt) {
#pragma unroll
        for (int i = 0; i < 2; ++i) {
            const int row = bm0 + wm + mt * 16 + gid + i * 8;
#pragma unroll
            for (int nt = 0; nt < 8; ++nt) {
                const int cl = wn + nt * 8 + 2 * tig;
                float v0 = fmaxf(acc[mt][nt][2 * i + 0] + bias_sm[cl], 0.f);
                float v1 = fmaxf(acc[mt][nt][2 * i + 1] + bias_sm[cl + 1], 0.f);
                *(__half2*)(C + (size_t)row * DH_ + cl) = __floats2half2_rn(v0, v1);
            }
        }
    }
}

// ===========================================================================
// GEMM2: out = softplus(h @ W2 + b2) * cv. fp16-ACC MMA (m16n8k16 f16),
// promoted to fp32 master accumulators after each kt (K-chunk=64).
// 128x128 tile, BK=64, 256 thr, 3-stage ring; final iter prefetches ret tile
// into dead slots 0-1; exact GARCH recurrence scanned in smem (seeded by cvs).
// ===========================================================================
#define G2_BK 64
#define G2_ST (2 * TILE_BYTES)            // 36864
#define G2_SMEM (3 * G2_ST)               // 110592
#define CVSTR 132

__global__ void __launch_bounds__(256, 2) gemm2_tc(
    const __half* __restrict__ A, const __half* __restrict__ Bt,
    const float* __restrict__ bias,
    const float* __restrict__ RET, const float* __restrict__ CVS,
    const float* __restrict__ pa, const float* __restrict__ pb,
    const float* __restrict__ pw,
    float* __restrict__ Cf)
{
    extern __shared__ char smraw[];
    const uint32_t sbase = smem_u32(smraw);
    float* cv_sm = (float*)smraw;          // overlays slots 0-1 post-mainloop
    __shared__ float bias_sm[128];

    const int N = D_, K = DH_;
    const int tid  = threadIdx.x;
    const int lane = tid & 31;
    const int warp = tid >> 5;
    const int wm   = (warp >> 2) * 64;    // 2x4 warp grid, 64x32 per warp
    const int wn   = (warp & 3) * 32;
    const int gid  = lane >> 2;
    const int tig  = lane & 3;
    const int bm0  = blockIdx.y * 128;
    const int bn0  = blockIdx.x * 128;
    const int nk   = K / G2_BK;           // 4
    const int OFF  = (2 - ((nk - 1) % 3) + 3) % 3;   // st(nk-1) == 2

    if (tid < 128) bias_sm[tid] = bias[bn0 + tid];

    float accm[4][4][4];                  // fp32 master
    uint32_t acch[4][4][2];               // fp16x2 chunk accumulators
#pragma unroll
    for (int mt = 0; mt < 4; ++mt)
#pragma unroll
        for (int nt = 0; nt < 4; ++nt) {
#pragma unroll
            for (int i = 0; i < 4; ++i) accm[mt][nt][i] = 0.f;
            acch[mt][nt][0] = 0u;
            acch[mt][nt][1] = 0u;
        }

    auto load_stage = [&](int kt) {
        const uint32_t tb = sbase + (uint32_t)(((kt + OFF) % 3) * G2_ST);
#pragma unroll
        for (int i = 0; i < 4; ++i) {
            const int id = tid + i * 256;
            const int r = id >> 3, s = id & 7;
            cp16(tb + r * ROWB + s * 16,
                 A + (size_t)(bm0 + r) * K + kt * G2_BK + s * 8);
        }
#pragma unroll
        for (int i = 0; i < 4; ++i) {
            const int id = tid + i * 256;
            const int r = id >> 3, s = id & 7;
            cp16(tb + TILE_BYTES + r * ROWB + s * 16,
                 Bt + (size_t)(bn0 + r) * K + kt * G2_BK + s * 8);
        }
        CP_COMMIT();
    };

    const int half = lane >> 3;
    const uint32_t laneA = (uint32_t)((wm + (lane & 7) + (half & 1) * 8) * ROWB
                                      + (half >> 1) * 16);
    const uint32_t laneB = (uint32_t)((wn + (lane & 7) + ((lane >> 4) << 3)) * ROWB
                                      + ((half & 1) * 16));

    load_stage(0);
    load_stage(1);

    for (int kt = 0; kt < nk; ++kt) {
        if (kt + 1 < nk) { CP_WAIT(1); } else { CP_WAIT(0); }
        __syncthreads();
        const uint32_t aB = sbase + (uint32_t)(((kt + OFF) % 3) * G2_ST);
        const uint32_t bB = aB + TILE_BYTES;
        if (kt + 2 < nk) load_stage(kt + 2);

        if (kt == nk - 1) {
            const float* Rg = RET + (size_t)bm0 * D_ + bn0;
#pragma unroll
            for (int i = 0; i < 16; ++i) {     // 4096 16B chunks
                const int id = tid + i * 256;
                const int r = id >> 5, s = id & 31;
                cp16(sbase + (uint32_t)(r * (CVSTR * 4) + s * 16),
                     Rg + (size_t)r * D_ + s * 4);
            }
            CP_COMMIT();
        }

#pragma unroll
        for (int q = 0; q < 4; ++q) {
            uint32_t bf[2][4];
#pragma unroll
            for (int p = 0; p < 2; ++p)
                LDSM_X4(bf[p][0], bf[p][1], bf[p][2], bf[p][3],
                        bB + laneB + p * (16 * ROWB) + q * 32);
            uint32_t af[4][4];
#pragma unroll
            for (int mt = 0; mt < 4; ++mt)
                LDSM_X4(af[mt][0], af[mt][1], af[mt][2], af[mt][3],
                        aB + laneA + mt * (16 * ROWB) + q * 32);
#pragma unroll
            for (int mt = 0; mt < 4; ++mt)
#pragma unroll
                for (int nt = 0; nt < 4; ++nt)
                    MMA16816H(acch[mt][nt], af[mt],
                              bf[nt >> 1][(nt & 1) * 2],
                              bf[nt >> 1][(nt & 1) * 2 + 1]);
        }

        // promote chunk (K=64) fp16 partials into fp32 masters, rezero
#pragma unroll
        for (int mt = 0; mt < 4; ++mt)
#pragma unroll
            for (int nt = 0; nt < 4; ++nt) {
                float2 lo = u2f2(acch[mt][nt][0]);
                float2 hi = u2f2(acch[mt][nt][1]);
                accm[mt][nt][0] += lo.x;
                accm[mt][nt][1] += lo.y;
                accm[mt][nt][2] += hi.x;
                accm[mt][nt][3] += hi.y;
                acch[mt][nt][0] = 0u;
                acch[mt][nt][1] = 0u;
            }
    }

    // in-block GARCH scan over reused stage smem
    CP_WAIT(0);
    __syncthreads();
    if (tid < 128) {
        const float alpha = pa[0], beta = pb[0], omega = pw[0];
        const int b = bm0 >> 12;
        const int chunk = (bm0 >> 7) & (NC_ - 1);
        const size_t cvsbase = (size_t)(((b << 5) + chunk) << 9);
        float p = CVS[cvsbase + bn0 + tid];
#pragma unroll 8
        for (int k = 0; k < CL_; ++k) {
            const int idx = k * CVSTR + tid;
            float r = cv_sm[idx];
            cv_sm[idx] = p;
            p = fmaf(beta, p, fmaf(alpha, r * r, omega));
        }
    }
    __syncthreads();

    // epilogue
#pragma unroll
    for (int mt = 0; mt < 4; ++mt) {
#pragma unroll
        for (int i = 0; i < 2; ++i) {
            const int rl  = wm + mt * 16 + gid + i * 8;
            const int row = bm0 + rl;
#pragma unroll
            for (int nt = 0; nt < 4; ++nt) {
                const int cl = wn + nt * 8 + 2 * tig;
                float v0 = accm[mt][nt][2 * i + 0] + bias_sm[cl];
                float v1 = accm[mt][nt][2 * i + 1] + bias_sm[cl + 1];
                const float2 cv = *(const float2*)&cv_sm[rl * CVSTR + cl];
                v0 = softplus_f(v0) * cv.x;
                v1 = softplus_f(v1) * cv.y;
                *(float2*)(Cf + (size_t)row * N + bn0 + cl) = make_float2(v0, v1);
            }
        }
    }
}

// ===========================================================================
extern "C" void kernel_launch(void* const* d_in, const int* in_sizes, int n_in,
                              void* d_out, int out_size)
{
    const float* x   = (const float*)d_in[0];
    const float* ret = (const float*)d_in[1];
    const float* al  = (const float*)d_in[2];
    const float* be  = (const float*)d_in[3];
    const float* om  = (const float*)d_in[4];
    const float* W1  = (const float*)d_in[5];
    const float* b1  = (const float*)d_in[6];
    const float* W2  = (const float*)d_in[7];
    const float* b2  = (const float*)d_in[8];
    float* out = (float*)d_out;

    __half *h, *w1t, *w2t;
    float *cvs;
    cudaGetSymbolAddress((void**)&h,   g_h);
    cudaGetSymbolAddress((void**)&cvs, g_cvs);
    cudaGetSymbolAddress((void**)&w1t, g_w1t);
    cudaGetSymbolAddress((void**)&w2t, g_w2t);

    cudaFuncSetAttribute(gemm1_tc, cudaFuncAttributeMaxDynamicSharedMemorySize, G1_SMEM);
    cudaFuncSetAttribute(gemm2_tc, cudaFuncAttributeMaxDynamicSharedMemorySize, G2_SMEM);

    // Side stream (R13 footprint: 1 stream, 3 events) for W2T + GARCH chain.
    cudaStream_t s2;
    cudaEvent_t evF, evJ;
    cudaStreamCreateWithFlags(&s2, cudaStreamNonBlocking);
    cudaEventCreateWithFlags(&evF, cudaEventDisableTiming);
    cudaEventCreateWithFlags(&evJ, cudaEventDisableTiming);

    cudaEventRecord(evF, 0);
    cudaStreamWaitEvent(s2, evF, 0);
    transpose_h_kernel<<<dim3(DH_ / 32, D_ / 32), dim3(32, 8), 0, s2>>>(W2, w2t, DH_, D_);
    garch_carry_kernel<<<(B_ * NC_ * D_ / 4) / 256, 256, 0, s2>>>(ret, al, be, om);
    garch_scan_kernel<<<(B_ * D_) / 256, 256, 0, s2>>>(be);
    cudaEventRecord(evJ, s2);

    transpose_h_kernel<<<dim3(D_ / 32, DH_ / 32), dim3(32, 8)>>>(W1, w1t, D_, DH_);
    gemm1_tc<<<dim3(1, M_ / G1_A_ROWS), 256, G1_SMEM>>>(x, w1t, b1, h);

    cudaStreamWaitEvent(0, evJ, 0);
    gemm2_tc<<<dim3(D_ / 128, M_ / 128), 256, G2_SMEM>>>(
        h, w2t, b2, ret, cvs, al, be, om, out);
}

// round 16
// speedup vs baseline: 1.0550x; 1.0550x over previous
#include <cuda_runtime.h>
#include <cuda_fp16.h>
#include <cstdint>
#include <math.h>

#define B_  16
#define S_  4096
#define D_  512
#define DH_ 256
#define M_  (B_ * S_)   // 65536
#define CL_ 128
#define NC_ 32

// Scratch (device globals; allocation-free per harness rules)
__device__ __half g_h[(size_t)M_ * DH_];       // 32 MB intermediate h (fp16)
__device__ float  g_carry[B_ * NC_ * D_];
__device__ float  g_cvs[B_ * NC_ * D_];
__device__ __half g_w1t[DH_ * D_];             // W1^T [256,512] (n-major, k-contig)
__device__ __half g_w2t[D_ * DH_];             // W2^T [512,256]

// ===========================================================================
// helpers
// ===========================================================================
__device__ __forceinline__ uint32_t smem_u32(const void* p) {
    uint32_t a;
    asm("{ .reg .u64 t; cvta.to.shared.u64 t, %1; cvt.u32.u64 %0, t; }"
        : "=r"(a) : "l"(p));
    return a;
}

__device__ __forceinline__ uint32_t h2u(__half2 v) {
    uint32_t u;
    __builtin_memcpy(&u, &v, 4);
    return u;
}

__device__ __forceinline__ void cp16(uint32_t dst, const void* src) {
    asm volatile("cp.async.cg.shared.global [%0], [%1], 16;" :: "r"(dst), "l"(src));
}
#define CP_COMMIT() asm volatile("cp.async.commit_group;" ::: "memory")
#define CP_WAIT(n)  asm volatile("cp.async.wait_group %0;" :: "n"(n) : "memory")

#define LDSM_X4(r0, r1, r2, r3, addr) \
    asm volatile("ldmatrix.sync.aligned.m8n8.x4.shared.b16 {%0,%1,%2,%3}, [%4];" \
        : "=r"(r0), "=r"(r1), "=r"(r2), "=r"(r3) : "r"(addr))

#define MMA16816(acc, a, b0, b1) \
    asm volatile( \
        "mma.sync.aligned.m16n8k16.row.col.f32.f16.f16.f32 " \
        "{%0,%1,%2,%3},{%4,%5,%6,%7},{%8,%9},{%0,%1,%2,%3};" \
        : "+f"((acc)[0]), "+f"((acc)[1]), "+f"((acc)[2]), "+f"((acc)[3]) \
        : "r"((a)[0]), "r"((a)[1]), "r"((a)[2]), "r"((a)[3]), \
          "r"(b0), "r"(b1))

// fast softplus: max(z,0) + log(1 + exp(-|z|)) via MUFU intrinsics
__device__ __forceinline__ float softplus_f(float z) {
    return fmaxf(z, 0.f) + __logf(1.f + __expf(-fabsf(z)));
}

// ===========================================================================
// GARCH carry pass (float4: 4 independent chains per thread, LDG.128)
// ===========================================================================
__global__ void __launch_bounds__(256) garch_carry_kernel(
    const float* __restrict__ ret,
    const float* __restrict__ pa, const float* __restrict__ pb,
    const float* __restrict__ pw)
{
    const int t  = blockIdx.x * 256 + threadIdx.x;   // 0..65535
    const int d4 = t & 127;
    const int c  = (t >> 7) & (NC_ - 1);
    const int b  = t >> 12;
    const float alpha = pa[0], beta = pb[0], omega = pw[0];
    const float4* rp = (const float4*)ret
                     + ((size_t)b * S_ + (size_t)c * CL_) * (D_ / 4) + d4;
    float4 p = make_float4(0.f, 0.f, 0.f, 0.f);
#pragma unroll 8
    for (int k = 0; k < CL_; ++k) {
        float4 r = rp[(size_t)k * (D_ / 4)];
        p.x = fmaf(beta, p.x, fmaf(alpha, r.x * r.x, omega));
        p.y = fmaf(beta, p.y, fmaf(alpha, r.y * r.y, omega));
        p.z = fmaf(beta, p.z, fmaf(alpha, r.z * r.z, omega));
        p.w = fmaf(beta, p.w, fmaf(alpha, r.w * r.w, omega));
    }
    ((float4*)g_carry)[(((b << 5) + c) << 7) + d4] = p;
}

// ===========================================================================
// GARCH scan: preload all 32 carries (MLP=32), then register scan.
// ===========================================================================
__global__ void __launch_bounds__(256) garch_scan_kernel(const float* __restrict__ pb)
{
    const int t = blockIdx.x * 256 + threadIdx.x;
    const int b = t >> 9;
    const int d = t & (D_ - 1);
    const float beta = pb[0];
    float A = 1.f;
#pragma unroll
    for (int i = 0; i < CL_; ++i) A *= beta;

    float ca[NC_];
#pragma unroll
    for (int c = 0; c < NC_; ++c)
        ca[c] = g_carry[(((b << 5) + c) << 9) + d];

    float cvs = 0.01f;
#pragma unroll
    for (int c = 0; c < NC_; ++c) {
        g_cvs[(((b << 5) + c) << 9) + d] = cvs;
        cvs = fmaf(A, cvs, ca[c]);
    }
}

// ===========================================================================
// Weight transpose [K,N] fp32 -> [N,K] fp16
// ===========================================================================
__global__ void transpose_h_kernel(const float* __restrict__ src, __half* __restrict__ dst,
                                   int K, int N)
{
    __shared__ float t[32][33];
    const int kb = blockIdx.x * 32, nb = blockIdx.y * 32;
    for (int i = threadIdx.y; i < 32; i += 8)
        t[i][threadIdx.x] = src[(size_t)(kb + i) * N + nb + threadIdx.x];
    __syncthreads();
    for (int i = threadIdx.y; i < 32; i += 8)
        dst[(size_t)(nb + i) * K + kb + threadIdx.x] = __float2half(t[threadIdx.x][i]);
}

// common geometry
#define ROWB 144                          // fp16 smem row stride (bytes)
#define TILE_BYTES (128 * ROWB)           // 18432 (128 rows)

// ===========================================================================
// GEMM1 (R13 + hoisted A prefetch): h = relu(x @ W1 + b1). Tile 64x256,
// 256 thr, 8 warps (2x4 grid, 32x64/warp), 2 CTAs/SM. A (x) fp32 from GMEM:
// LDG.128 prefetch (issued BEFORE the cp.async wait) -> cvt fp16 -> STS
// double-buffered. B: 2-stage cp.async ring.
// ===========================================================================
#define G1_BK 64
#define G1_A_ROWS 64
#define G1_A16_ST (G1_A_ROWS * ROWB)               // 9216, 2 stages
#define G1_B_ROWS 256
#define G1_B_ST (G1_B_ROWS * ROWB)                 // 36864, 2 stages
#define G1_SMEM (2 * G1_A16_ST + 2 * G1_B_ST)      // 92160

__global__ void __launch_bounds__(256, 2) gemm1_tc(
    const float* __restrict__ X, const __half* __restrict__ Bt,
    const float* __restrict__ bias, __half* __restrict__ C)
{
    extern __shared__ char smraw[];
    const uint32_t sbase = smem_u32(smraw);
    const uint32_t a16b  = sbase;                   // 2 x 9216
    const uint32_t bb    = sbase + 2 * G1_A16_ST;   // 2 x 36864
    __shared__ float bias_sm[256];

    const int tid  = threadIdx.x;
    const int lane = tid & 31;
    const int warp = tid >> 5;
    const int wm   = (warp >> 2) * 32;    // 2x4 warp grid, 32x64 per warp
    const int wn   = (warp & 3) * 64;
    const int gid  = lane >> 2;
    const int tig  = lane & 3;
    const int bm0  = blockIdx.y * G1_A_ROWS;
    const int nk   = D_ / G1_BK;          // 8

    bias_sm[tid] = bias[tid];

    float acc[2][8][4];
#pragma unroll
    for (int mt = 0; mt < 2; ++mt)
#pragma unroll
        for (int nt = 0; nt < 8; ++nt)
#pragma unroll
            for (int i = 0; i < 4; ++i) acc[mt][nt][i] = 0.f;

    auto load_B = [&](int kt) {
        const uint32_t tb = bb + (uint32_t)((kt & 1) * G1_B_ST);
#pragma unroll
        for (int i = 0; i < 8; ++i) {          // 2048 16B chunks
            const int id = tid + i * 256;
            const int r = id >> 3, s = id & 7;
            cp16(tb + r * ROWB + s * 16,
                 Bt + (size_t)r * D_ + kt * G1_BK + s * 8);
        }
        CP_COMMIT();
    };

    const int arow = tid >> 2;            // 0..63
    const int aq   = tid & 3;
    const float* Xrow = X + (size_t)(bm0 + arow) * D_ + aq * 16;
    const uint32_t a16w = (uint32_t)(arow * ROWB + aq * 32);   // 16 halves

    auto ldg_A = [&](int kt, float4* pf) {
#pragma unroll
        for (int i = 0; i < 4; ++i)
            pf[i] = *(const float4*)(Xrow + kt * G1_BK + i * 4);
    };
    auto sts_A = [&](int kt, const float4* pf) {
        const uint32_t dst = a16b + (uint32_t)((kt & 1) * G1_A16_ST) + a16w;
        uint32_t h[8];
#pragma unroll
        for (int i = 0; i < 4; ++i) {
            h[2 * i]     = h2u(__floats2half2_rn(pf[i].x, pf[i].y));
            h[2 * i + 1] = h2u(__floats2half2_rn(pf[i].z, pf[i].w));
        }
        asm volatile("st.shared.v4.b32 [%0], {%1,%2,%3,%4};"
                     :: "r"(dst), "r"(h[0]), "r"(h[1]), "r"(h[2]), "r"(h[3]));
        asm volatile("st.shared.v4.b32 [%0], {%1,%2,%3,%4};"
                     :: "r"(dst + 16), "r"(h[4]), "r"(h[5]), "r"(h[6]), "r"(h[7]));
    };

    // prologue: B stage 0; A stage 0
    load_B(0);
    {
        float4 pf[4];
        ldg_A(0, pf);
        sts_A(0, pf);
    }

    const int half = lane >> 3;
    const uint32_t laneA = (uint32_t)((wm + (lane & 7) + (half & 1) * 8) * ROWB
                                      + (half >> 1) * 16);
    const uint32_t laneB = (uint32_t)((wn + (lane & 7) + ((lane >> 4) << 3)) * ROWB
                                      + ((half & 1) * 16));

    for (int kt = 0; kt < nk; ++kt) {
        // hoisted: next-A global prefetch starts before the wait/barrier
        float4 pf[4];
        if (kt + 1 < nk) ldg_A(kt + 1, pf);

        CP_WAIT(0);
        __syncthreads();                       // B[kt] arrived, A16[kt] visible

        if (kt + 1 < nk) load_B(kt + 1);       // fill other B slot

        const uint32_t aB = a16b + (uint32_t)((kt & 1) * G1_A16_ST);
        const uint32_t bB = bb + (uint32_t)((kt & 1) * G1_B_ST);

#pragma unroll
        for (int q = 0; q < 4; ++q) {          // 4 k16 sub-steps
            uint32_t af[2][4];
#pragma unroll
            for (int mt = 0; mt < 2; ++mt)
                LDSM_X4(af[mt][0], af[mt][1], af[mt][2], af[mt][3],
                        aB + laneA + mt * (16 * ROWB) + q * 32);
#pragma unroll
            for (int p = 0; p < 4; ++p) {      // 4 B x4 loads -> 8 n8 frags
                uint32_t bf[4];
                LDSM_X4(bf[0], bf[1], bf[2], bf[3],
                        bB + laneB + p * (16 * ROWB) + q * 32);
#pragma unroll
                for (int mt = 0; mt < 2; ++mt) {
                    MMA16816(acc[mt][2 * p],     af[mt], bf[0], bf[1]);
                    MMA16816(acc[mt][2 * p + 1], af[mt], bf[2], bf[3]);
                }
            }
        }

        if (kt + 1 < nk) sts_A(kt + 1, pf);    // convert into other A16 buffer
    }

    // epilogue: relu + fp16 store
#pragma unroll
    for (int mt = 0; mt < 2; ++mt) {
#pragma unroll
        for (int i = 0; i < 2; ++i) {
            const int row = bm0 + wm + mt * 16 + gid + i * 8;
#pragma unroll
            for (int nt = 0; nt < 8; ++nt) {
                const int cl = wn + nt * 8 + 2 * tig;
                float v0 = fmaxf(acc[mt][nt][2 * i + 0] + bias_sm[cl], 0.f);
                float v1 = fmaxf(acc[mt][nt][2 * i + 1] + bias_sm[cl + 1], 0.f);
                *(__half2*)(C + (size_t)row * DH_ + cl) = __floats2half2_rn(v0, v1);
            }
        }
    }
}

// ===========================================================================
// GEMM2 (proven R13, fp32-acc): out = softplus(h @ W2 + b2) * cv. fp16 MMA,
// 128x128 tile, BK=64, 256 thr (2x4 warp grid, 64x32/warp), 3-stage ring;
// final iter computes from slot 2 while prefetching the ret tile into dead
// slots 0-1; then exact GARCH recurrence scanned in smem (seeded by cvs).
// ===========================================================================
#define G2_BK 64
#define G2_ST (2 * TILE_BYTES)            // 36864
#define G2_SMEM (3 * G2_ST)               // 110592
#define CVSTR 132

__global__ void __launch_bounds__(256, 2) gemm2_tc(
    const __half* __restrict__ A, const __half* __restrict__ Bt,
    const float* __restrict__ bias,
    const float* __restrict__ RET, const float* __restrict__ CVS,
    const float* __restrict__ pa, const float* __restrict__ pb,
    const float* __restrict__ pw,
    float* __restrict__ Cf)
{
    extern __shared__ char smraw[];
    const uint32_t sbase = smem_u32(smraw);
    float* cv_sm = (float*)smraw;          // overlays slots 0-1 post-mainloop
    __shared__ float bias_sm[128];

    const int N = D_, K = DH_;
    const int tid  = threadIdx.x;
    const int lane = tid & 31;
    const int warp = tid >> 5;
    const int wm   = (warp >> 2) * 64;    // 2x4 warp grid, 64x32 per warp
    const int wn   = (warp & 3) * 32;
    const int gid  = lane >> 2;
    const int tig  = lane & 3;
    const int bm0  = blockIdx.y * 128;
    const int bn0  = blockIdx.x * 128;
    const int nk   = K / G2_BK;           // 4
    const int OFF  = (2 - ((nk - 1) % 3) + 3) % 3;   // st(nk-1) == 2

    if (tid < 128) bias_sm[tid] = bias[bn0 + tid];

    float acc[4][4][4];
#pragma unroll
    for (int mt = 0; mt < 4; ++mt)
#pragma unroll
        for (int nt = 0; nt < 4; ++nt)
#pragma unroll
            for (int i = 0; i < 4; ++i) acc[mt][nt][i] = 0.f;

    auto load_stage = [&](int kt) {
        const uint32_t tb = sbase + (uint32_t)(((kt + OFF) % 3) * G2_ST);
#pragma unroll
        for (int i = 0; i < 4; ++i) {
            const int id = tid + i * 256;
            const int r = id >> 3, s = id & 7;
            cp16(tb + r * ROWB + s * 16,
                 A + (size_t)(bm0 + r) * K + kt * G2_BK + s * 8);
        }
#pragma unroll
        for (int i = 0; i < 4; ++i) {
            const int id = tid + i * 256;
            const int r = id >> 3, s = id & 7;
            cp16(tb + TILE_BYTES + r * ROWB + s * 16,
                 Bt + (size_t)(bn0 + r) * K + kt * G2_BK + s * 8);
        }
        CP_COMMIT();
    };

    const int half = lane >> 3;
    const uint32_t laneA = (uint32_t)((wm + (lane & 7) + (half & 1) * 8) * ROWB
                                      + (half >> 1) * 16);
    const uint32_t laneB = (uint32_t)((wn + (lane & 7) + ((lane >> 4) << 3)) * ROWB
                                      + ((half & 1) * 16));

    load_stage(0);
    load_stage(1);

    for (int kt = 0; kt < nk; ++kt) {
        if (kt + 1 < nk) { CP_WAIT(1); } else { CP_WAIT(0); }
        __syncthreads();
        const uint32_t aB = sbase + (uint32_t)(((kt + OFF) % 3) * G2_ST);
        const uint32_t bB = aB + TILE_BYTES;
        if (kt + 2 < nk) load_stage(kt + 2);

        if (kt == nk - 1) {
            const float* Rg = RET + (size_t)bm0 * D_ + bn0;
#pragma unroll
            for (int i = 0; i < 16; ++i) {     // 4096 16B chunks
                const int id = tid + i * 256;
                const int r = id >> 5, s = id & 31;
                cp16(sbase + (uint32_t)(r * (CVSTR * 4) + s * 16),
                     Rg + (size_t)r * D_ + s * 4);
            }
            CP_COMMIT();
        }

#pragma unroll
        for (int q = 0; q < 4; ++q) {
            uint32_t bf[2][4];
#pragma unroll
            for (int p = 0; p < 2; ++p)
                LDSM_X4(bf[p][0], bf[p][1], bf[p][2], bf[p][3],
                        bB + laneB + p * (16 * ROWB) + q * 32);
            uint32_t af[4][4];
#pragma unroll
            for (int mt = 0; mt < 4; ++mt)
                LDSM_X4(af[mt][0], af[mt][1], af[mt][2], af[mt][3],
                        aB + laneA + mt * (16 * ROWB) + q * 32);
#pragma unroll
            for (int mt = 0; mt < 4; ++mt)
#pragma unroll
                for (int nt = 0; nt < 4; ++nt)
                    MMA16816(acc[mt][nt], af[mt],
                             bf[nt >> 1][(nt & 1) * 2],
                             bf[nt >> 1][(nt & 1) * 2 + 1]);
        }
    }

    // in-block GARCH scan over reused stage smem
    CP_WAIT(0);
    __syncthreads();
    if (tid < 128) {
        const float alpha = pa[0], beta = pb[0], omega = pw[0];
        const int b = bm0 >> 12;
        const int chunk = (bm0 >> 7) & (NC_ - 1);
        const size_t cvsbase = (size_t)(((b << 5) + chunk) << 9);
        float p = CVS[cvsbase + bn0 + tid];
#pragma unroll 8
        for (int k = 0; k < CL_; ++k) {
            const int idx = k * CVSTR + tid;
            float r = cv_sm[idx];
            cv_sm[idx] = p;
            p = fmaf(beta, p, fmaf(alpha, r * r, omega));
        }
    }
    __syncthreads();

    // epilogue
#pragma unroll
    for (int mt = 0; mt < 4; ++mt) {
#pragma unroll
        for (int i = 0; i < 2; ++i) {
            const int rl  = wm + mt * 16 + gid + i * 8;
            const int row = bm0 + rl;
#pragma unroll
            for (int nt = 0; nt < 4; ++nt) {
                const int cl = wn + nt * 8 + 2 * tig;
                float v0 = acc[mt][nt][2 * i + 0] + bias_sm[cl];
                float v1 = acc[mt][nt][2 * i + 1] + bias_sm[cl + 1];
                const float2 cv = *(const float2*)&cv_sm[rl * CVSTR + cl];
                v0 = softplus_f(v0) * cv.x;
                v1 = softplus_f(v1) * cv.y;
                *(float2*)(Cf + (size_t)row * N + bn0 + cl) = make_float2(v0, v1);
            }
        }
    }
}

// ===========================================================================
extern "C" void kernel_launch(void* const* d_in, const int* in_sizes, int n_in,
                              void* d_out, int out_size)
{
    const float* x   = (const float*)d_in[0];
    const float* ret = (const float*)d_in[1];
    const float* al  = (const float*)d_in[2];
    const float* be  = (const float*)d_in[3];
    const float* om  = (const float*)d_in[4];
    const float* W1  = (const float*)d_in[5];
    const float* b1  = (const float*)d_in[6];
    const float* W2  = (const float*)d_in[7];
    const float* b2  = (const float*)d_in[8];
    float* out = (float*)d_out;

    __half *h, *w1t, *w2t;
    float *cvs;
    cudaGetSymbolAddress((void**)&h,   g_h);
    cudaGetSymbolAddress((void**)&cvs, g_cvs);
    cudaGetSymbolAddress((void**)&w1t, g_w1t);
    cudaGetSymbolAddress((void**)&w2t, g_w2t);

    cudaFuncSetAttribute(gemm1_tc, cudaFuncAttributeMaxDynamicSharedMemorySize, G1_SMEM);
    cudaFuncSetAttribute(gemm2_tc, cudaFuncAttributeMaxDynamicSharedMemorySize, G2_SMEM);

    // Side stream (R13 footprint: 1 stream, 2 events) for W2T + GARCH chain.
    cudaStream_t s2;
    cudaEvent_t evF, evJ;
    cudaStreamCreateWithFlags(&s2, cudaStreamNonBlocking);
    cudaEventCreateWithFlags(&evF, cudaEventDisableTiming);
    cudaEventCreateWithFlags(&evJ, cudaEventDisableTiming);

    cudaEventRecord(evF, 0);
    cudaStreamWaitEvent(s2, evF, 0);
    transpose_h_kernel<<<dim3(DH_ / 32, D_ / 32), dim3(32, 8), 0, s2>>>(W2, w2t, DH_, D_);
    garch_carry_kernel<<<(B_ * NC_ * D_ / 4) / 256, 256, 0, s2>>>(ret, al, be, om);
    garch_scan_kernel<<<(B_ * D_) / 256, 256, 0, s2>>>(be);
    cudaEventRecord(evJ, s2);

    transpose_h_kernel<<<dim3(D_ / 32, DH_ / 32), dim3(32, 8)>>>(W1, w1t, D_, DH_);
    gemm1_tc<<<dim3(1, M_ / G1_A_ROWS), 256, G1_SMEM>>>(x, w1t, b1, h);

    cudaStreamWaitEvent(0, evJ, 0);
    gemm2_tc<<<dim3(D_ / 128, M_ / 128), 256, G2_SMEM>>>(
        h, w2t, b2, ret, cvs, al, be, om, out);
}